// round 2
// baseline (speedup 1.0000x reference)
#include <cuda_runtime.h>
#include <math_constants.h>

#define APW 1024            // atoms per warp (contiguous chunk)
#define THREADS_MAIN 256    // 8 warps per block

// Scratch: per-segment atom counts. BATCH = out_size/256 = 16384; pad to 64K.
__device__ float g_counts[65536];

__device__ __forceinline__ void atomic_max_float(float* addr, float v) {
    // Works given init to -inf: non-negative floats order as ints,
    // negative floats reverse-order as unsigned ints.
    if (v >= 0.0f) atomicMax((int*)addr, __float_as_int(v));
    else           atomicMin((unsigned int*)addr, __float_as_uint(v));
}

// ---------------------------------------------------------------------------
// Init: mean half = 0 (sum accumulator), max half = -inf, counts = 0
// ---------------------------------------------------------------------------
__global__ void gg_init(float* __restrict__ out, int batch) {
    int i = blockIdx.x * blockDim.x + threadIdx.x;
    int total = batch * 256;
    if (i < total) out[i] = ((i & 255) < 128) ? 0.0f : -CUDART_INF_F;
    if (i < batch) g_counts[i] = 0.0f;
}

// ---------------------------------------------------------------------------
// Main: warp-per-chunk segmented scan.
// Lane l owns features [4l, 4l+4) via float4. Interior segments (begin AND
// end inside this warp's chunk) flush with plain stores; boundary segments
// flush with atomics.
// ---------------------------------------------------------------------------
__global__ void gg_main(const float* __restrict__ feat,
                        const int*   __restrict__ mem,
                        float*       __restrict__ out,
                        int n_atoms) {
    const int lane = threadIdx.x & 31;
    const long long wg = (long long)((blockIdx.x * blockDim.x + threadIdx.x) >> 5);
    long long astart = wg * APW;
    if (astart >= n_atoms) return;
    long long aend = astart + APW;
    if (aend > n_atoms) aend = n_atoms;

    const float4* __restrict__ frow = (const float4*)feat;  // 32 float4 per row

    int  seg = __ldg(mem + astart);
    bool began_inside = (astart == 0) || (__ldg(mem + astart - 1) != seg);

    float4 s = make_float4(0.f, 0.f, 0.f, 0.f);
    float4 m = make_float4(-CUDART_INF_F, -CUDART_INF_F, -CUDART_INF_F, -CUDART_INF_F);
    int cnt = 0;

    auto flush = [&](int sg, bool full) {
        float* om = out + (size_t)sg * 256 + lane * 4;   // mean(sum) slot
        float* ox = om + 128;                            // max slot
        if (full) {
            *(float4*)om = s;
            *(float4*)ox = m;
            if (lane == 0) g_counts[sg] = (float)cnt;
        } else {
            atomicAdd(om + 0, s.x); atomicAdd(om + 1, s.y);
            atomicAdd(om + 2, s.z); atomicAdd(om + 3, s.w);
            atomic_max_float(ox + 0, m.x); atomic_max_float(ox + 1, m.y);
            atomic_max_float(ox + 2, m.z); atomic_max_float(ox + 3, m.w);
            if (lane == 0) atomicAdd(&g_counts[sg], (float)cnt);
        }
    };

    long long a = astart;
    // Unroll-8 main loop: batch all loads first for MLP=8 LDG.128 per lane.
    for (; a + 8 <= aend; a += 8) {
        int4 mb0 = *(const int4*)(mem + a);
        int4 mb1 = *(const int4*)(mem + a + 4);
        float4 vv[8];
#pragma unroll
        for (int u = 0; u < 8; ++u)
            vv[u] = __ldg(&frow[(a + u) * 32 + lane]);
        int mbs[8] = {mb0.x, mb0.y, mb0.z, mb0.w, mb1.x, mb1.y, mb1.z, mb1.w};
#pragma unroll
        for (int u = 0; u < 8; ++u) {
            if (mbs[u] != seg) {
                // segment ended inside chunk -> full iff it also began inside
                flush(seg, began_inside);
                began_inside = true;
                seg = mbs[u];
                s = make_float4(0.f, 0.f, 0.f, 0.f);
                m = make_float4(-CUDART_INF_F, -CUDART_INF_F, -CUDART_INF_F, -CUDART_INF_F);
                cnt = 0;
            }
            s.x += vv[u].x; s.y += vv[u].y; s.z += vv[u].z; s.w += vv[u].w;
            m.x = fmaxf(m.x, vv[u].x); m.y = fmaxf(m.y, vv[u].y);
            m.z = fmaxf(m.z, vv[u].z); m.w = fmaxf(m.w, vv[u].w);
            ++cnt;
        }
    }
    // Scalar tail (only if chunk size not divisible by 8)
    for (; a < aend; ++a) {
        int mb = __ldg(mem + a);
        float4 v = __ldg(&frow[a * 32 + lane]);
        if (mb != seg) {
            flush(seg, began_inside);
            began_inside = true;
            seg = mb;
            s = make_float4(0.f, 0.f, 0.f, 0.f);
            m = make_float4(-CUDART_INF_F, -CUDART_INF_F, -CUDART_INF_F, -CUDART_INF_F);
            cnt = 0;
        }
        s.x += v.x; s.y += v.y; s.z += v.z; s.w += v.w;
        m.x = fmaxf(m.x, v.x); m.y = fmaxf(m.y, v.y);
        m.z = fmaxf(m.z, v.z); m.w = fmaxf(m.w, v.w);
        ++cnt;
    }

    bool ended_inside = (aend == n_atoms) || (__ldg(mem + aend) != seg);
    flush(seg, began_inside && ended_inside);
}

// ---------------------------------------------------------------------------
// Finalize: mean = sum / count (max half already final)
// ---------------------------------------------------------------------------
__global__ void gg_fin(float* __restrict__ out, int batch) {
    int i = blockIdx.x * blockDim.x + threadIdx.x;
    if (i < batch * 128) {
        int sg = i >> 7;
        int f  = i & 127;
        out[(size_t)sg * 256 + f] *= (1.0f / g_counts[sg]);
    }
}

// ---------------------------------------------------------------------------
extern "C" void kernel_launch(void* const* d_in, const int* in_sizes, int n_in,
                              void* d_out, int out_size) {
    const float* feat = (const float*)d_in[0];
    const int*   mem  = (const int*)d_in[1];
    float*       out  = (float*)d_out;

    int n_atoms = in_sizes[1];          // membership element count
    int batch   = out_size / 256;       // output rows ([batch, 2*128])

    int init_total = batch * 256;
    gg_init<<<(init_total + 255) / 256, 256>>>(out, batch);

    long long nwarps   = ((long long)n_atoms + APW - 1) / APW;
    long long nthreads = nwarps * 32;
    int nblocks = (int)((nthreads + THREADS_MAIN - 1) / THREADS_MAIN);
    gg_main<<<nblocks, THREADS_MAIN>>>(feat, mem, out, n_atoms);

    int fin_total = batch * 128;
    gg_fin<<<(fin_total + 255) / 256, 256>>>(out, batch);
}